// round 9
// baseline (speedup 1.0000x reference)
#include <cuda_runtime.h>
#include <cuda_bf16.h>
#include <cuda_fp16.h>
#include <cstdint>
#include <cstddef>

#define NNODES 50000
#define NFEAT  128
#define KTOP   32
#define EDGES  800000
#define FULLM  0xFFFFFFFFu

// ---------------- device scratch (no allocation allowed) ----------------
__device__ int   g_cnt[NNODES];
__device__ int   g_rowstart[NNODES];
__device__ int   g_cursor[NNODES];
__device__ int   g_col[EDGES];
__device__ __align__(16) __half g_Yh[NNODES * NFEAT];   // Y = Xsp @ W_neigh (fp16)

// ===========================================================================
// CSR build (by dst): histogram -> single-kernel scan -> fill
// ===========================================================================
__global__ void count_kernel(const int* __restrict__ dst, int e) {
    int i = blockIdx.x * blockDim.x + threadIdx.x;
    int base = i * 4;
    if (base + 3 < e) {
        int4 d = *(const int4*)(dst + base);
        atomicAdd(&g_cnt[d.x], 1);
        atomicAdd(&g_cnt[d.y], 1);
        atomicAdd(&g_cnt[d.z], 1);
        atomicAdd(&g_cnt[d.w], 1);
    } else {
        for (int j = base; j < e; j++) atomicAdd(&g_cnt[dst[j]], 1);
    }
}

// single block, 1024 threads: chunked exclusive scan of g_cnt -> rowstart/cursor
__global__ __launch_bounds__(1024)
void scan_kernel(int n) {
    __shared__ int sh[1024];
    int t = threadIdx.x;
    const int chunk = (n + 1023) / 1024;
    int lo = t * chunk;
    int hi = min(lo + chunk, n);
    int s = 0;
    for (int i = lo; i < hi; i++) s += g_cnt[i];
    sh[t] = s;
    __syncthreads();
#pragma unroll
    for (int o = 1; o < 1024; o <<= 1) {
        int x = (t >= o) ? sh[t - o] : 0;
        __syncthreads();
        sh[t] += x;
        __syncthreads();
    }
    int run = sh[t] - s;   // exclusive prefix of this chunk
    for (int i = lo; i < hi; i++) {
        g_rowstart[i] = run;
        g_cursor[i]   = run;
        run += g_cnt[i];
    }
}

__global__ void fill_kernel(const int* __restrict__ src, const int* __restrict__ dst, int e) {
    int i = blockIdx.x * blockDim.x + threadIdx.x;
    if (i < e) {
        int pos = atomicAdd(&g_cursor[dst[i]], 1);
        g_col[pos] = src[i];
    }
}

// ===========================================================================
// y_kernel: Y[row] = x_sparse[row] @ W_neigh, dedup (last-k-wins), fp16 out
// ===========================================================================
__global__ __launch_bounds__(256)
void y_kernel(const int* __restrict__ tindices,
              const float* __restrict__ tvalues,
              const float* __restrict__ Wneigh, int n) {
    int wrp  = blockIdx.x * 8 + (threadIdx.x >> 5);
    int lane = threadIdx.x & 31;
    if (wrp >= n) return;
    int   idx = tindices[wrp * KTOP + lane];
    float v   = tvalues[wrp * KTOP + lane];
    unsigned m = __match_any_sync(FULLM, idx);
    if (lane != 31 - __clz(m)) v = 0.0f;

    float4 acc = make_float4(0.f, 0.f, 0.f, 0.f);
#pragma unroll
    for (int k = 0; k < KTOP; k++) {
        int   ik = __shfl_sync(FULLM, idx, k);
        float vk = __shfl_sync(FULLM, v, k);
        if (vk != 0.0f) {
            float4 w = __ldg((const float4*)(Wneigh + ik * NFEAT) + lane);
            acc.x = fmaf(vk, w.x, acc.x);
            acc.y = fmaf(vk, w.y, acc.y);
            acc.z = fmaf(vk, w.z, acc.z);
            acc.w = fmaf(vk, w.w, acc.w);
        }
    }
    __half2 h0 = __floats2half2_rn(acc.x, acc.y);
    __half2 h1 = __floats2half2_rn(acc.z, acc.w);
    uint2 o;
    o.x = *(uint32_t*)&h0;
    o.y = *(uint32_t*)&h1;
    *((uint2*)(g_Yh + (size_t)wrp * NFEAT) + lane) = o;
}

// ===========================================================================
// gather_add: out[d] += (1/max(deg,1)) * sum Y[s]   (fp16 in / fp32 RMW out)
// ===========================================================================
__global__ __launch_bounds__(256)
void gather_add_kernel(float* __restrict__ out, int n) {
    int d    = blockIdx.x * 8 + (threadIdx.x >> 5);
    int lane = threadIdx.x & 31;
    if (d >= n) return;
    int cnt = g_cnt[d];
    if (cnt == 0) return;           // out row already correct (agg = 0)
    int start = g_rowstart[d];

    float4 o = *((const float4*)(out + (size_t)d * NFEAT) + lane);
    float4 acc = make_float4(0.f, 0.f, 0.f, 0.f);
    for (int i = 0; i < cnt; i += 32) {
        int s = (i + lane < cnt) ? g_col[start + i + lane] : 0;
        int m = min(32, cnt - i);
        int j = 0;
        for (; j + 4 <= m; j += 4) {
#pragma unroll
            for (int q = 0; q < 4; q++) {
                int sj = __shfl_sync(FULLM, s, j + q);
                uint2 y = *((const uint2*)(g_Yh + (size_t)sj * NFEAT) + lane);
                float2 f0 = __half22float2(*(__half2*)&y.x);
                float2 f1 = __half22float2(*(__half2*)&y.y);
                acc.x += f0.x; acc.y += f0.y; acc.z += f1.x; acc.w += f1.y;
            }
        }
        for (; j < m; j++) {
            int sj = __shfl_sync(FULLM, s, j);
            uint2 y = *((const uint2*)(g_Yh + (size_t)sj * NFEAT) + lane);
            float2 f0 = __half22float2(*(__half2*)&y.x);
            float2 f1 = __half22float2(*(__half2*)&y.y);
            acc.x += f0.x; acc.y += f0.y; acc.z += f1.x; acc.w += f1.y;
        }
    }
    float w = 1.0f / (float)cnt;
    o.x = fmaf(acc.x, w, o.x);
    o.y = fmaf(acc.y, w, o.y);
    o.z = fmaf(acc.z, w, o.z);
    o.w = fmaf(acc.w, w, o.w);
    *((float4*)(out + (size_t)d * NFEAT) + lane) = o;
}

// ===========================================================================
// gemm_mma: out = feat @ W_self + b_self   (mma.sync bf16 split, 3 passes)
// CTA: 128x128 tile. 8 warps 4(m) x 2(n): warp tile 32x64. K chunks of 64.
// ===========================================================================
#define SOFF_A_HI 0
#define SOFF_A_LO 16384
#define SOFF_B_HI 32768
#define SOFF_B_LO 49152
#define GEMM_SMEM 65536

__device__ __forceinline__ uint32_t pkbf(__nv_bfloat16 a, __nv_bfloat16 b) {
    return (uint32_t)__bfloat16_as_ushort(a) | ((uint32_t)__bfloat16_as_ushort(b) << 16);
}

__device__ __forceinline__ void ldsm4(uint32_t* r, uint32_t addr) {
    asm volatile("ldmatrix.sync.aligned.m8n8.x4.shared.b16 {%0,%1,%2,%3}, [%4];"
                 : "=r"(r[0]), "=r"(r[1]), "=r"(r[2]), "=r"(r[3]) : "r"(addr));
}

__device__ __forceinline__ void mma16816(float* d, const uint32_t* a, const uint32_t* b) {
    asm volatile(
        "mma.sync.aligned.m16n8k16.row.col.f32.bf16.bf16.f32 "
        "{%0,%1,%2,%3}, {%4,%5,%6,%7}, {%8,%9}, {%0,%1,%2,%3};"
        : "+f"(d[0]), "+f"(d[1]), "+f"(d[2]), "+f"(d[3])
        : "r"(a[0]), "r"(a[1]), "r"(a[2]), "r"(a[3]), "r"(b[0]), "r"(b[1]));
}

__global__ __launch_bounds__(256)
void gemm_mma(const float* __restrict__ feat,
              const float* __restrict__ Wself,
              const float* __restrict__ bself,
              float* __restrict__ out, int n) {
    extern __shared__ char smem[];
    const uint32_t sb  = (uint32_t)__cvta_generic_to_shared(smem);
    const int tid  = threadIdx.x;
    const int row0 = blockIdx.x * 128;
    const int wid  = tid >> 5;
    const int lane = tid & 31;
    const int wm   = wid & 3;
    const int wn   = wid >> 2;

    float acc[2][8][4];
#pragma unroll
    for (int a = 0; a < 2; a++)
#pragma unroll
        for (int b = 0; b < 8; b++)
#pragma unroll
            for (int c = 0; c < 4; c++) acc[a][b][c] = 0.0f;

#pragma unroll 1
    for (int k0 = 0; k0 < NFEAT; k0 += 64) {
        // ---- stage A (128 rows x 64 k) hi/lo bf16, swizzled ----
#pragma unroll 2
        for (int i = 0; i < 8; i++) {
            int f   = tid + i * 256;
            int row = f >> 4;
            int kq  = f & 15;
            int gr  = min(row0 + row, n - 1);
            float4 v = __ldg((const float4*)feat + (size_t)gr * 32 + (k0 >> 2) + kq);
            __nv_bfloat16 h0 = __float2bfloat16(v.x), h1 = __float2bfloat16(v.y);
            __nv_bfloat16 h2 = __float2bfloat16(v.z), h3 = __float2bfloat16(v.w);
            __nv_bfloat16 l0 = __float2bfloat16(v.x - __bfloat162float(h0));
            __nv_bfloat16 l1 = __float2bfloat16(v.y - __bfloat162float(h1));
            __nv_bfloat16 l2 = __float2bfloat16(v.z - __bfloat162float(h2));
            __nv_bfloat16 l3 = __float2bfloat16(v.w - __bfloat162float(h3));
            uint2 hv, lv;
            hv.x = pkbf(h0, h1); hv.y = pkbf(h2, h3);
            lv.x = pkbf(l0, l1); lv.y = pkbf(l2, l3);
            uint32_t off = (uint32_t)row * 128
                         + ((((uint32_t)(kq >> 1)) ^ ((uint32_t)row & 7)) << 4)
                         + ((kq & 1) << 3);
            *(uint2*)(smem + SOFF_A_HI + off) = hv;
            *(uint2*)(smem + SOFF_A_LO + off) = lv;
        }
        // ---- stage B: Bt[n][k] = Wself[k0+k][n], swizzled, hi/lo ----
        {
            int nn = tid & 127;
            int kg = (tid >> 7) << 5;
            const float* wp = Wself + (size_t)(k0 + kg) * NFEAT + nn;
#pragma unroll 2
            for (int j0 = 0; j0 < 32; j0 += 8) {
                uint32_t hv[4], lv[4];
#pragma unroll
                for (int q = 0; q < 4; q++) {
                    float x0 = __ldg(wp + (j0 + 2 * q) * NFEAT);
                    float x1 = __ldg(wp + (j0 + 2 * q + 1) * NFEAT);
                    __nv_bfloat16 a0 = __float2bfloat16(x0), a1 = __float2bfloat16(x1);
                    __nv_bfloat16 b0 = __float2bfloat16(x0 - __bfloat162float(a0));
                    __nv_bfloat16 b1 = __float2bfloat16(x1 - __bfloat162float(a1));
                    hv[q] = pkbf(a0, a1);
                    lv[q] = pkbf(b0, b1);
                }
                uint32_t off = (uint32_t)nn * 128
                             + ((((uint32_t)((kg + j0) >> 3)) ^ ((uint32_t)nn & 7)) << 4);
                *(uint4*)(smem + SOFF_B_HI + off) = *(uint4*)hv;
                *(uint4*)(smem + SOFF_B_LO + off) = *(uint4*)lv;
            }
        }
        __syncthreads();

#pragma unroll
        for (int ks = 0; ks < 4; ks++) {
            uint32_t ah[2][4], al[2][4];
            {
                int arow = wm * 32 + (lane & 7) + ((lane >> 3) & 1) * 8;
                int ak8  = ks * 2 + (lane >> 4);
                uint32_t aoff = (uint32_t)arow * 128
                              + (((uint32_t)ak8 ^ ((uint32_t)arow & 7)) << 4);
                ldsm4(ah[0], sb + SOFF_A_HI + aoff);
                ldsm4(ah[1], sb + SOFF_A_HI + aoff + 2048);
                ldsm4(al[0], sb + SOFF_A_LO + aoff);
                ldsm4(al[1], sb + SOFF_A_LO + aoff + 2048);
            }
            int nrow0 = wn * 64 + (lane & 7) + ((lane >> 4) & 1) * 8;
            int bk8   = ks * 2 + ((lane >> 3) & 1);
#pragma unroll
            for (int np = 0; np < 4; np++) {
                int nrow = nrow0 + np * 16;
                uint32_t boff = (uint32_t)nrow * 128
                              + (((uint32_t)bk8 ^ ((uint32_t)nrow & 7)) << 4);
                uint32_t bh[4], bl[4];
                ldsm4(bh, sb + SOFF_B_HI + boff);
                ldsm4(bl, sb + SOFF_B_LO + boff);
#pragma unroll
                for (int mt = 0; mt < 2; mt++) {
                    mma16816(acc[mt][np * 2 + 0], ah[mt], bh + 0);
                    mma16816(acc[mt][np * 2 + 0], ah[mt], bl + 0);
                    mma16816(acc[mt][np * 2 + 0], al[mt], bh + 0);
                    mma16816(acc[mt][np * 2 + 1], ah[mt], bh + 2);
                    mma16816(acc[mt][np * 2 + 1], ah[mt], bl + 2);
                    mma16816(acc[mt][np * 2 + 1], al[mt], bh + 2);
                }
            }
        }
        __syncthreads();
    }

    // ---- epilogue: + bias only (neighbor term added by gather_add) ----
    const int qrow = lane >> 2;
    const int qcol = (lane & 3) * 2;
#pragma unroll
    for (int mt = 0; mt < 2; mt++) {
        int r1 = row0 + wm * 32 + mt * 16 + qrow;
        int r2 = r1 + 8;
#pragma unroll
        for (int nt = 0; nt < 8; nt++) {
            int col = wn * 64 + nt * 8 + qcol;
            float2 b = *(const float2*)(bself + col);
            if (r1 < n) {
                float2 o;
                o.x = acc[mt][nt][0] + b.x;
                o.y = acc[mt][nt][1] + b.y;
                *(float2*)(out + (size_t)r1 * NFEAT + col) = o;
            }
            if (r2 < n) {
                float2 o;
                o.x = acc[mt][nt][2] + b.x;
                o.y = acc[mt][nt][3] + b.y;
                *(float2*)(out + (size_t)r2 * NFEAT + col) = o;
            }
        }
    }
}

// ===========================================================================
// Launch: single stream (graph-capture-safe, no stream/event creation).
//   memset -> count -> scan -> fill -> y -> gemm -> gather_add
// Inputs: 0 feat | 1 topk_values | 2 topk_indices | 3 src | 4 dst |
//         5 W_self | 6 b_self | 7 W_neigh
// ===========================================================================
extern "C" void kernel_launch(void* const* d_in, const int* in_sizes, int n_in,
                              void* d_out, int out_size) {
    const float* feat     = (const float*)d_in[0];
    const float* tvalues  = (const float*)d_in[1];
    const int*   tindices = (const int*)d_in[2];
    const int*   src      = (const int*)d_in[3];
    const int*   dst      = (const int*)d_in[4];
    const float* Wself    = (const float*)d_in[5];
    const float* bself    = (const float*)d_in[6];
    const float* Wneigh   = (const float*)d_in[7];
    float*       out      = (float*)d_out;

    const int n = in_sizes[0] / NFEAT;   // 50000
    const int e = in_sizes[3];           // 800000

    cudaFuncSetAttribute(gemm_mma, cudaFuncAttributeMaxDynamicSharedMemorySize,
                         GEMM_SMEM);

    void* cntp;
    cudaGetSymbolAddress(&cntp, g_cnt);
    cudaMemsetAsync(cntp, 0, (size_t)n * sizeof(int));

    count_kernel<<<(e / 4 + 255) / 256, 256>>>(dst, e);
    scan_kernel<<<1, 1024>>>(n);
    fill_kernel<<<(e + 255) / 256, 256>>>(src, dst, e);

    y_kernel<<<(n + 7) / 8, 256>>>(tindices, tvalues, Wneigh, n);
    gemm_mma<<<(n + 127) / 128, 256, GEMM_SMEM>>>(feat, Wself, bself, out, n);
    gather_add_kernel<<<(n + 7) / 8, 256>>>(out, n);
}

// round 11
// speedup vs baseline: 1.0430x; 1.0430x over previous
#include <cuda_runtime.h>
#include <cuda_bf16.h>
#include <cuda_fp16.h>
#include <cstdint>
#include <cstddef>

#define NNODES 50000
#define NFEAT  128
#define KTOP   32
#define EDGES  800000
#define FULLM  0xFFFFFFFFu

// ---------------- device scratch (no allocation allowed) ----------------
__device__ int   g_cnt[NNODES];
__device__ int   g_rowstart[NNODES];
__device__ int   g_cursor[NNODES];
__device__ int   g_col[EDGES];
__device__ __align__(16) __half         g_Yh[NNODES * NFEAT];  // Y = Xsp @ W_neigh (fp16)
__device__ __align__(16) __nv_bfloat16  g_Wn[NFEAT * NFEAT];   // W_neigh in bf16

// ===========================================================================
// K1 (fused): blocks [0,16): convert W_neigh fp32->bf16
//             blocks [16,...): in-degree histogram over dst (int4-vectorized)
// ===========================================================================
#define CONV_BLOCKS 16
__global__ void conv_count_kernel(const float* __restrict__ Wneigh,
                                  const int* __restrict__ dst, int e) {
    if (blockIdx.x < CONV_BLOCKS) {
        int i = blockIdx.x * 256 + threadIdx.x;   // 4096 threads x 4 elems
#pragma unroll
        for (int q = 0; q < 4; q++) {
            int idx = i * 4 + q;
            g_Wn[idx] = __float2bfloat16(Wneigh[idx]);
        }
    } else {
        int i = (blockIdx.x - CONV_BLOCKS) * blockDim.x + threadIdx.x;
        int base = i * 4;
        if (base + 3 < e) {
            int4 d = *(const int4*)(dst + base);
            atomicAdd(&g_cnt[d.x], 1);
            atomicAdd(&g_cnt[d.y], 1);
            atomicAdd(&g_cnt[d.z], 1);
            atomicAdd(&g_cnt[d.w], 1);
        } else {
            for (int j = base; j < e; j++) atomicAdd(&g_cnt[dst[j]], 1);
        }
    }
}

// ===========================================================================
// K2: single block, 1024 threads: chunked exclusive scan -> rowstart/cursor
// ===========================================================================
__global__ __launch_bounds__(1024)
void scan_kernel(int n) {
    __shared__ int sh[1024];
    int t = threadIdx.x;
    const int chunk = (n + 1023) / 1024;
    int lo = t * chunk;
    int hi = min(lo + chunk, n);
    int s = 0;
    for (int i = lo; i < hi; i++) s += g_cnt[i];
    sh[t] = s;
    __syncthreads();
#pragma unroll
    for (int o = 1; o < 1024; o <<= 1) {
        int x = (t >= o) ? sh[t - o] : 0;
        __syncthreads();
        sh[t] += x;
        __syncthreads();
    }
    int run = sh[t] - s;
    for (int i = lo; i < hi; i++) {
        g_rowstart[i] = run;
        g_cursor[i]   = run;
        run += g_cnt[i];
    }
}

// ===========================================================================
// K3 (fused): blocks [0, yblk): Y[row] = x_sparse[row] @ W_neigh_bf16
//                               (dedup last-k-wins, fp32 acc, fp16 out)
//             blocks [yblk,..): CSR fill (int4-vectorized edge read)
// ===========================================================================
__global__ __launch_bounds__(256)
void y_fill_kernel(const int* __restrict__ tindices,
                   const float* __restrict__ tvalues,
                   const int* __restrict__ src,
                   const int* __restrict__ dst,
                   int n, int e, int yblk) {
    if (blockIdx.x < yblk) {
        int wrp  = blockIdx.x * 8 + (threadIdx.x >> 5);
        int lane = threadIdx.x & 31;
        if (wrp >= n) return;
        int   idx = tindices[wrp * KTOP + lane];
        float v   = tvalues[wrp * KTOP + lane];
        unsigned m = __match_any_sync(FULLM, idx);
        if (lane != 31 - __clz(m)) v = 0.0f;   // highest-k lane wins duplicates

        float4 acc = make_float4(0.f, 0.f, 0.f, 0.f);
#pragma unroll
        for (int k = 0; k < KTOP; k++) {
            int   ik = __shfl_sync(FULLM, idx, k);
            float vk = __shfl_sync(FULLM, v, k);
            if (vk != 0.0f) {   // warp-uniform
                uint2 w = __ldg((const uint2*)(g_Wn + ik * NFEAT) + lane);
                __nv_bfloat162 w0 = *(__nv_bfloat162*)&w.x;
                __nv_bfloat162 w1 = *(__nv_bfloat162*)&w.y;
                acc.x = fmaf(vk, __bfloat162float(w0.x), acc.x);
                acc.y = fmaf(vk, __bfloat162float(w0.y), acc.y);
                acc.z = fmaf(vk, __bfloat162float(w1.x), acc.z);
                acc.w = fmaf(vk, __bfloat162float(w1.y), acc.w);
            }
        }
        __half2 h0 = __floats2half2_rn(acc.x, acc.y);
        __half2 h1 = __floats2half2_rn(acc.z, acc.w);
        uint2 o;
        o.x = *(uint32_t*)&h0;
        o.y = *(uint32_t*)&h1;
        *((uint2*)(g_Yh + (size_t)wrp * NFEAT) + lane) = o;
    } else {
        int i = (blockIdx.x - yblk) * blockDim.x + threadIdx.x;
        int base = i * 4;
        if (base + 3 < e) {
            int4 d = *(const int4*)(dst + base);
            int4 s = *(const int4*)(src + base);
            g_col[atomicAdd(&g_cursor[d.x], 1)] = s.x;
            g_col[atomicAdd(&g_cursor[d.y], 1)] = s.y;
            g_col[atomicAdd(&g_cursor[d.z], 1)] = s.z;
            g_col[atomicAdd(&g_cursor[d.w], 1)] = s.w;
        } else {
            for (int j = base; j < e; j++)
                g_col[atomicAdd(&g_cursor[dst[j]], 1)] = src[j];
        }
    }
}

// ===========================================================================
// gather_add: out[d] += (1/deg) * sum Y[s]   (fp16 in / fp32 RMW out)
// ===========================================================================
__global__ __launch_bounds__(256)
void gather_add_kernel(float* __restrict__ out, int n) {
    int d    = blockIdx.x * 8 + (threadIdx.x >> 5);
    int lane = threadIdx.x & 31;
    if (d >= n) return;
    int cnt = g_cnt[d];
    if (cnt == 0) return;           // out row already correct (agg = 0)
    int start = g_rowstart[d];

    float4 o = *((const float4*)(out + (size_t)d * NFEAT) + lane);
    float4 acc = make_float4(0.f, 0.f, 0.f, 0.f);
    for (int i = 0; i < cnt; i += 32) {
        int s = (i + lane < cnt) ? g_col[start + i + lane] : 0;
        int m = min(32, cnt - i);
        int j = 0;
        for (; j + 4 <= m; j += 4) {
#pragma unroll
            for (int q = 0; q < 4; q++) {
                int sj = __shfl_sync(FULLM, s, j + q);
                uint2 y = *((const uint2*)(g_Yh + (size_t)sj * NFEAT) + lane);
                float2 f0 = __half22float2(*(__half2*)&y.x);
                float2 f1 = __half22float2(*(__half2*)&y.y);
                acc.x += f0.x; acc.y += f0.y; acc.z += f1.x; acc.w += f1.y;
            }
        }
        for (; j < m; j++) {
            int sj = __shfl_sync(FULLM, s, j);
            uint2 y = *((const uint2*)(g_Yh + (size_t)sj * NFEAT) + lane);
            float2 f0 = __half22float2(*(__half2*)&y.x);
            float2 f1 = __half22float2(*(__half2*)&y.y);
            acc.x += f0.x; acc.y += f0.y; acc.z += f1.x; acc.w += f1.y;
        }
    }
    float w = 1.0f / (float)cnt;
    o.x = fmaf(acc.x, w, o.x);
    o.y = fmaf(acc.y, w, o.y);
    o.z = fmaf(acc.z, w, o.z);
    o.w = fmaf(acc.w, w, o.w);
    *((float4*)(out + (size_t)d * NFEAT) + lane) = o;
}

// ===========================================================================
// gemm_mma: out = feat @ W_self + b_self   (mma.sync bf16 split, 3 passes)
// ===========================================================================
#define SOFF_A_HI 0
#define SOFF_A_LO 16384
#define SOFF_B_HI 32768
#define SOFF_B_LO 49152
#define GEMM_SMEM 65536

__device__ __forceinline__ uint32_t pkbf(__nv_bfloat16 a, __nv_bfloat16 b) {
    return (uint32_t)__bfloat16_as_ushort(a) | ((uint32_t)__bfloat16_as_ushort(b) << 16);
}

__device__ __forceinline__ void ldsm4(uint32_t* r, uint32_t addr) {
    asm volatile("ldmatrix.sync.aligned.m8n8.x4.shared.b16 {%0,%1,%2,%3}, [%4];"
                 : "=r"(r[0]), "=r"(r[1]), "=r"(r[2]), "=r"(r[3]) : "r"(addr));
}

__device__ __forceinline__ void mma16816(float* d, const uint32_t* a, const uint32_t* b) {
    asm volatile(
        "mma.sync.aligned.m16n8k16.row.col.f32.bf16.bf16.f32 "
        "{%0,%1,%2,%3}, {%4,%5,%6,%7}, {%8,%9}, {%0,%1,%2,%3};"
        : "+f"(d[0]), "+f"(d[1]), "+f"(d[2]), "+f"(d[3])
        : "r"(a[0]), "r"(a[1]), "r"(a[2]), "r"(a[3]), "r"(b[0]), "r"(b[1]));
}

__global__ __launch_bounds__(256)
void gemm_mma(const float* __restrict__ feat,
              const float* __restrict__ Wself,
              const float* __restrict__ bself,
              float* __restrict__ out, int n) {
    extern __shared__ char smem[];
    const uint32_t sb  = (uint32_t)__cvta_generic_to_shared(smem);
    const int tid  = threadIdx.x;
    const int row0 = blockIdx.x * 128;
    const int wid  = tid >> 5;
    const int lane = tid & 31;
    const int wm   = wid & 3;
    const int wn   = wid >> 2;

    float acc[2][8][4];
#pragma unroll
    for (int a = 0; a < 2; a++)
#pragma unroll
        for (int b = 0; b < 8; b++)
#pragma unroll
            for (int c = 0; c < 4; c++) acc[a][b][c] = 0.0f;

#pragma unroll 1
    for (int k0 = 0; k0 < NFEAT; k0 += 64) {
#pragma unroll 2
        for (int i = 0; i < 8; i++) {
            int f   = tid + i * 256;
            int row = f >> 4;
            int kq  = f & 15;
            int gr  = min(row0 + row, n - 1);
            float4 v = __ldg((const float4*)feat + (size_t)gr * 32 + (k0 >> 2) + kq);
            __nv_bfloat16 h0 = __float2bfloat16(v.x), h1 = __float2bfloat16(v.y);
            __nv_bfloat16 h2 = __float2bfloat16(v.z), h3 = __float2bfloat16(v.w);
            __nv_bfloat16 l0 = __float2bfloat16(v.x - __bfloat162float(h0));
            __nv_bfloat16 l1 = __float2bfloat16(v.y - __bfloat162float(h1));
            __nv_bfloat16 l2 = __float2bfloat16(v.z - __bfloat162float(h2));
            __nv_bfloat16 l3 = __float2bfloat16(v.w - __bfloat162float(h3));
            uint2 hv, lv;
            hv.x = pkbf(h0, h1); hv.y = pkbf(h2, h3);
            lv.x = pkbf(l0, l1); lv.y = pkbf(l2, l3);
            uint32_t off = (uint32_t)row * 128
                         + ((((uint32_t)(kq >> 1)) ^ ((uint32_t)row & 7)) << 4)
                         + ((kq & 1) << 3);
            *(uint2*)(smem + SOFF_A_HI + off) = hv;
            *(uint2*)(smem + SOFF_A_LO + off) = lv;
        }
        {
            int nn = tid & 127;
            int kg = (tid >> 7) << 5;
            const float* wp = Wself + (size_t)(k0 + kg) * NFEAT + nn;
#pragma unroll 2
            for (int j0 = 0; j0 < 32; j0 += 8) {
                uint32_t hv[4], lv[4];
#pragma unroll
                for (int q = 0; q < 4; q++) {
                    float x0 = __ldg(wp + (j0 + 2 * q) * NFEAT);
                    float x1 = __ldg(wp + (j0 + 2 * q + 1) * NFEAT);
                    __nv_bfloat16 a0 = __float2bfloat16(x0), a1 = __float2bfloat16(x1);
                    __nv_bfloat16 b0 = __float2bfloat16(x0 - __bfloat162float(a0));
                    __nv_bfloat16 b1 = __float2bfloat16(x1 - __bfloat162float(a1));
                    hv[q] = pkbf(a0, a1);
                    lv[q] = pkbf(b0, b1);
                }
                uint32_t off = (uint32_t)nn * 128
                             + ((((uint32_t)((kg + j0) >> 3)) ^ ((uint32_t)nn & 7)) << 4);
                *(uint4*)(smem + SOFF_B_HI + off) = *(uint4*)hv;
                *(uint4*)(smem + SOFF_B_LO + off) = *(uint4*)lv;
            }
        }
        __syncthreads();

#pragma unroll
        for (int ks = 0; ks < 4; ks++) {
            uint32_t ah[2][4], al[2][4];
            {
                int arow = wm * 32 + (lane & 7) + ((lane >> 3) & 1) * 8;
                int ak8  = ks * 2 + (lane >> 4);
                uint32_t aoff = (uint32_t)arow * 128
                              + (((uint32_t)ak8 ^ ((uint32_t)arow & 7)) << 4);
                ldsm4(ah[0], sb + SOFF_A_HI + aoff);
                ldsm4(ah[1], sb + SOFF_A_HI + aoff + 2048);
                ldsm4(al[0], sb + SOFF_A_LO + aoff);
                ldsm4(al[1], sb + SOFF_A_LO + aoff + 2048);
            }
            int nrow0 = wn * 64 + (lane & 7) + ((lane >> 4) & 1) * 8;
            int bk8   = ks * 2 + ((lane >> 3) & 1);
#pragma unroll
            for (int np = 0; np < 4; np++) {
                int nrow = nrow0 + np * 16;
                uint32_t boff = (uint32_t)nrow * 128
                              + (((uint32_t)bk8 ^ ((uint32_t)nrow & 7)) << 4);
                uint32_t bh[4], bl[4];
                ldsm4(bh, sb + SOFF_B_HI + boff);
                ldsm4(bl, sb + SOFF_B_LO + boff);
#pragma unroll
                for (int mt = 0; mt < 2; mt++) {
                    mma16816(acc[mt][np * 2 + 0], ah[mt], bh + 0);
                    mma16816(acc[mt][np * 2 + 0], ah[mt], bl + 0);
                    mma16816(acc[mt][np * 2 + 0], al[mt], bh + 0);
                    mma16816(acc[mt][np * 2 + 1], ah[mt], bh + 2);
                    mma16816(acc[mt][np * 2 + 1], ah[mt], bl + 2);
                    mma16816(acc[mt][np * 2 + 1], al[mt], bh + 2);
                }
            }
        }
        __syncthreads();
    }

    const int qrow = lane >> 2;
    const int qcol = (lane & 3) * 2;
#pragma unroll
    for (int mt = 0; mt < 2; mt++) {
        int r1 = row0 + wm * 32 + mt * 16 + qrow;
        int r2 = r1 + 8;
#pragma unroll
        for (int nt = 0; nt < 8; nt++) {
            int col = wn * 64 + nt * 8 + qcol;
            float2 b = *(const float2*)(bself + col);
            if (r1 < n) {
                float2 o;
                o.x = acc[mt][nt][0] + b.x;
                o.y = acc[mt][nt][1] + b.y;
                *(float2*)(out + (size_t)r1 * NFEAT + col) = o;
            }
            if (r2 < n) {
                float2 o;
                o.x = acc[mt][nt][2] + b.x;
                o.y = acc[mt][nt][3] + b.y;
                *(float2*)(out + (size_t)r2 * NFEAT + col) = o;
            }
        }
    }
}

// ===========================================================================
// Launch: single stream, 5 launches + memset.
//   memset -> (conv|count) -> scan -> (y|fill) -> gemm -> gather_add
// Inputs: 0 feat | 1 topk_values | 2 topk_indices | 3 src | 4 dst |
//         5 W_self | 6 b_self | 7 W_neigh
// ===========================================================================
extern "C" void kernel_launch(void* const* d_in, const int* in_sizes, int n_in,
                              void* d_out, int out_size) {
    const float* feat     = (const float*)d_in[0];
    const float* tvalues  = (const float*)d_in[1];
    const int*   tindices = (const int*)d_in[2];
    const int*   src      = (const int*)d_in[3];
    const int*   dst      = (const int*)d_in[4];
    const float* Wself    = (const float*)d_in[5];
    const float* bself    = (const float*)d_in[6];
    const float* Wneigh   = (const float*)d_in[7];
    float*       out      = (float*)d_out;

    const int n = in_sizes[0] / NFEAT;   // 50000
    const int e = in_sizes[3];           // 800000

    cudaFuncSetAttribute(gemm_mma, cudaFuncAttributeMaxDynamicSharedMemorySize,
                         GEMM_SMEM);

    void* cntp;
    cudaGetSymbolAddress(&cntp, g_cnt);
    cudaMemsetAsync(cntp, 0, (size_t)n * sizeof(int));

    const int cntblk  = (e / 4 + 255) / 256;           // 782
    const int yblk    = (n + 7) / 8;                   // 6250
    const int fillblk = (e / 4 + 255) / 256;           // 782

    conv_count_kernel<<<CONV_BLOCKS + cntblk, 256>>>(Wneigh, dst, e);
    scan_kernel<<<1, 1024>>>(n);
    y_fill_kernel<<<yblk + fillblk, 256>>>(tindices, tvalues, src, dst, n, e, yblk);
    gemm_mma<<<(n + 127) / 128, 256, GEMM_SMEM>>>(feat, Wself, bself, out, n);
    gather_add_kernel<<<(n + 7) / 8, 256>>>(out, n);
}